// round 12
// baseline (speedup 1.0000x reference)
#include <cuda_runtime.h>
#include <math.h>

#define NCLS   20
#define NBINS  16
#define NANCH  21824
#define BATCH  16
#define MGT    32
#define NGT    (BATCH*MGT)

#define QFL_BLK    256
#define QFL_GX     ((NANCH + QFL_BLK - 1) / QFL_BLK)     // 86
#define REG_BLOCKS 16
#define REG_BLK    256

// global accumulators / scratch (no device mallocs allowed)
__device__ double g_qfl, g_dfl, g_giou;
__device__ int    g_pos;
__device__ unsigned int g_count;                 // ticket for sparse kernel
__device__ int    g_plcount;                     // positive-list size
__device__ int    g_matched[BATCH * NANCH];      // 0 = none, else m+1
__device__ int2   g_poslist[BATCH * NANCH];      // (b*NANCH+n, matched)

// analytic anchor decode: bit-exact vs the reference make_anchors()
__device__ __forceinline__ float4 anchor_from_idx(const int n) {
    const int l = (n >= 16384) + (n >= 20480) + (n >= 21504) + (n >= 21760);
    const int offs = (65536 - (65536 >> (2 * l))) / 3;
    const int shift = 7 - l;                  // log2(grid dim)
    const int r = n - offs;
    const int iy = r >> shift;
    const int ix = r - (iy << shift);
    const float s = (float)(8 << l);
    const float cx = (ix + 0.5f) * s;
    const float cy = (iy + 0.5f) * s;
    const float half = 2.0f * s;
    return make_float4(cx - half, cy - half, cx + half, cy + half);
}

// ---------------------------------------------------------------------------
// Warp-cooperative ATSS threshold (R7-validated, bit-identical thresholds).
// ---------------------------------------------------------------------------
__device__ __forceinline__ float atss_threshold(const float4 gt, const int lane) {
    const float gcx = 0.5f * (gt.x + gt.z);
    const float gcy = 0.5f * (gt.y + gt.w);

    float cd[4]; int ci[4];
#pragma unroll
    for (int j = 0; j < 4; j++) {
        const int c = lane + 32 * j;
        float nrm = 3.4e38f; int idx = 0x7fffffff;
        if (c < 125) {
            const int l   = c / 25;
            const int rem = c - 25 * l;
            const int dy  = rem / 5;
            const int dx  = rem - 5 * dy;
            const int   n    = 128 >> l;
            const float s    = (float)(8 << l);
            const int   offs = (65536 - (65536 >> (2 * l))) / 3;
            const int jcx = (int)floorf(gcx / s);
            const int jcy = (int)floorf(gcy / s);
            const int lx0 = min(max(jcx - 2, 0), n - 5);
            const int ly0 = min(max(jcy - 2, 0), n - 5);
            const int ix = lx0 + dx;
            const int iy = ly0 + dy;
            const float cx = (ix + 0.5f) * s;
            const float cy = (iy + 0.5f) * s;
            const float ddx = cx - gcx;
            const float ddy = cy - gcy;
            const float ddy2 = __fmul_rn(ddy, ddy);
            nrm = sqrtf(__fadd_rn(__fmul_rn(ddx, ddx), ddy2));
            idx = offs + iy * n + ix;
        }
        cd[j] = nrm; ci[j] = idx;
    }

    int my_win = 0;
#pragma unroll
    for (int r = 0; r < 9; r++) {
        float bd = cd[0]; int bi = ci[0]; int bs = 0;
#pragma unroll
        for (int k = 1; k < 4; k++) {
            const bool lt = (cd[k] < bd) || (cd[k] == bd && ci[k] < bi);
            if (lt) { bd = cd[k]; bi = ci[k]; bs = k; }
        }
        float wd = bd; int wi = bi;
#pragma unroll
        for (int off = 16; off > 0; off >>= 1) {
            const float od = __shfl_xor_sync(0xffffffffu, wd, off);
            const int   oi = __shfl_xor_sync(0xffffffffu, wi, off);
            if (od < wd || (od == wd && oi < wi)) { wd = od; wi = oi; }
        }
        if (lane == r) my_win = wi;
        if (bi == wi) {
#pragma unroll
            for (int k = 0; k < 4; k++)
                if (k == bs) { cd[k] = 3.4e38f; ci[k] = 0x7fffffff; }
        }
    }

    const float area_g = (gt.z - gt.x) * (gt.w - gt.y);
    float iou = 0.f;
    if (lane < 9) {
        const float4 ab = anchor_from_idx(my_win);
        const float area_a = (ab.z - ab.x) * (ab.w - ab.y);
        const float lx = fmaxf(ab.x, gt.x), ly = fmaxf(ab.y, gt.y);
        const float rx = fminf(ab.z, gt.z), ry = fminf(ab.w, gt.w);
        const float iw = fmaxf(rx - lx, 0.f), ih = fmaxf(ry - ly, 0.f);
        const float inter = iw * ih;
        const float uni = area_a + area_g - inter;
        iou = inter / fmaxf(uni, 1e-9f);
    }

    float v[9];
#pragma unroll
    for (int k = 0; k < 9; k++) v[k] = __shfl_sync(0xffffffffu, iou, k);
    float sum = 0.f;
#pragma unroll
    for (int k = 0; k < 9; k++) sum += v[k];
    const float mean = sum / 9.0f;
    float vs = 0.f;
#pragma unroll
    for (int k = 0; k < 9; k++) { const float t = v[k] - mean; vs += t * t; }
    return mean + sqrtf(vs / 8.0f);
}

// ---------------------------------------------------------------------------
// Phase A: one WARP per GT: threshold + scatter matches (atomicMax = last-
// GT-wins reference semantics). R10-validated.
// ---------------------------------------------------------------------------
__global__ void match_kernel(const float4* __restrict__ gt_boxes) {
    const int warp = threadIdx.x >> 5;
    const int lane = threadIdx.x & 31;
    const int g = blockIdx.x * 4 + warp;            // 128 blocks x 4 warps
    if (blockIdx.x == 0 && threadIdx.x == 0) {
        g_qfl = 0.0; g_dfl = 0.0; g_giou = 0.0; g_pos = 0; g_plcount = 0; // defensive
    }
    if (g >= NGT) return;

    const float4 gt = __ldg(&gt_boxes[g]);
    const float thr = atss_threshold(gt, lane);

    const int b = g >> 5;
    const int m = g & 31;
    int* mslice = g_matched + b * NANCH;
    const float area_g = (gt.z - gt.x) * (gt.w - gt.y);

#pragma unroll
    for (int l = 0; l < 5; l++) {
        const int   n    = 128 >> l;
        const float s    = (float)(8 << l);
        const float half = 2.0f * s;
        const int   offs = (65536 - (65536 >> (2 * l))) / 3;
        const int ix0 = max(0,     (int)floorf(gt.x / s - 0.5f) - 1);
        const int ix1 = min(n - 1, (int)ceilf (gt.z / s - 0.5f) + 1);
        const int iy0 = max(0,     (int)floorf(gt.y / s - 0.5f) - 1);
        const int iy1 = min(n - 1, (int)ceilf (gt.w / s - 0.5f) + 1);
        const int W = ix1 - ix0 + 1;
        const int H = iy1 - iy0 + 1;
        const int tot = W * H;
        for (int t = lane; t < tot; t += 32) {
            const int ty = t / W;
            const int iy = iy0 + ty;
            const int ix = ix0 + (t - ty * W);
            const float cx = (ix + 0.5f) * s;
            const float cy = (iy + 0.5f) * s;
            const bool inside = (cx >= gt.x) && (cx <= gt.z) &&
                                (cy >= gt.y) && (cy <= gt.w);
            if (inside) {
                const float ax = cx - half, ay = cy - half;
                const float az = cx + half, aw = cy + half;
                const float area_a = (az - ax) * (aw - ay);
                const float lx = fmaxf(ax, gt.x), ly = fmaxf(ay, gt.y);
                const float rx = fminf(az, gt.z), ry = fminf(aw, gt.w);
                const float iw = fmaxf(rx - lx, 0.f), ih = fmaxf(ry - ly, 0.f);
                const float inter = iw * ih;
                const float uni = area_a + area_g - inter;
                if (inter >= thr * uni)
                    atomicMax(&mslice[offs + iy * n + ix], m + 1);
            }
        }
    }
}

// ---------------------------------------------------------------------------
// Phase B: dense QFL-only kernel. Lean: no DFL/GIoU code. Reads g_matched
// (does NOT clear), recomputes matched IoU, pushes positives into g_poslist
// via warp-aggregated atomic, accumulates qfl + pos.
// ---------------------------------------------------------------------------
__global__ void qfl_kernel(const float* __restrict__ cls_preds,
                           const float4* __restrict__ gt_boxes,
                           const int* __restrict__ gt_labels) {
    __shared__ float4 sGT[MGT];
    __shared__ float  sArea[MGT];
    __shared__ int    sLab[MGT];
    const int b = blockIdx.y;
    if (threadIdx.x < MGT) {
        const float4 gbx = gt_boxes[b * MGT + threadIdx.x];
        sGT[threadIdx.x]   = gbx;
        sArea[threadIdx.x] = (gbx.z - gbx.x) * (gbx.w - gbx.y);
        sLab[threadIdx.x]  = gt_labels[b * MGT + threadIdx.x];
    }
    __syncthreads();

    const int n = blockIdx.x * blockDim.x + threadIdx.x;
    const bool valid = n < NANCH;
    const int lane = threadIdx.x & 31;
    const int warp = threadIdx.x >> 5;

    const int midx = b * NANCH + (valid ? n : 0);
    int mm = 0;
    if (valid) mm = g_matched[midx];
    const bool pos = valid && (mm > 0);
    const int matched = pos ? (mm - 1) : 0;

    float it = 0.f;
    if (pos) {
        const float4 a = anchor_from_idx(n);
        const float area_a = (a.z - a.x) * (a.w - a.y);
        const float4 gbx = sGT[matched];
        const float lx = fmaxf(a.x, gbx.x), ly = fmaxf(a.y, gbx.y);
        const float rx = fminf(a.z, gbx.z), ry = fminf(a.w, gbx.w);
        const float iw = fmaxf(rx - lx, 0.f), ih = fmaxf(ry - ly, 0.f);
        const float inter = iw * ih;
        const float uni = area_a + sArea[matched] - inter;
        it = inter / fmaxf(uni, 1e-9f);
    }

    // warp-aggregated push of positives
    const unsigned pm = __ballot_sync(0xffffffffu, pos);
    if (pos) {
        const int leader = __ffs(pm) - 1;
        const int rank = __popc(pm & ((1u << lane) - 1u));
        int base = 0;
        if (lane == leader) base = atomicAdd(&g_plcount, __popc(pm));
        base = __shfl_sync(pm, base, leader);
        g_poslist[base + rank] = make_int2(midx, matched);
    }

    // ---- Quality Focal Loss over 20 classes (fast-math; R5-validated) ----
    float qfl = 0.f;
    if (valid) {
        const int cls_t = pos ? sLab[matched] : 0;
        const float4* cp = (const float4*)(cls_preds + ((size_t)b * NANCH + n) * NCLS);
#pragma unroll
        for (int v = 0; v < 5; v++) {
            const float4 xv = __ldg(&cp[v]);
            const float xs[4] = { xv.x, xv.y, xv.z, xv.w };
#pragma unroll
            for (int j = 0; j < 4; j++) {
                const int c = v * 4 + j;
                const float x = xs[j];
                const bool tpos = (c == cls_t);
                const float e = __expf(-fabsf(x));
                const float sp = __logf(1.0f + e);
                const float r = __fdividef(1.0f, 1.0f + e);
                const float psig = (x >= 0.f) ? r : (1.0f - r);
                const float pt = tpos ? psig : (1.0f - psig);
                const float bce = fmaxf(x, 0.f) - (tpos ? x : 0.f) + sp;
                const float w = fmaf(it, 1.0f - 2.0f * pt, pt);
                qfl += w * w * bce;
            }
        }
    }

    int posi = pos ? 1 : 0;
#pragma unroll
    for (int off = 16; off > 0; off >>= 1) {
        qfl  += __shfl_xor_sync(0xffffffffu, qfl,  off);
        posi += __shfl_xor_sync(0xffffffffu, posi, off);
    }
    __shared__ float rq[8];
    __shared__ int   rp_[8];
    if (lane == 0) { rq[warp] = qfl; rp_[warp] = posi; }
    __syncthreads();
    if (threadIdx.x == 0) {
        float q = 0.f; int pp = 0;
#pragma unroll
        for (int wi = 0; wi < QFL_BLK / 32; wi++) { q += rq[wi]; pp += rp_[wi]; }
        if (q != 0.f) atomicAdd(&g_qfl, (double)q);
        if (pp != 0)  atomicAdd(&g_pos, pp);
    }
}

// ---------------------------------------------------------------------------
// Phase C: sparse kernel over the positive list: DFL + decode + GIoU
// (validated accurate math), clears g_matched entries, ticket finalize.
// ---------------------------------------------------------------------------
__global__ void reg_kernel(const float* __restrict__ reg_preds,
                           const float4* __restrict__ gt_boxes,
                           float* __restrict__ out) {
    float dfl = 0.f, giou_l = 0.f;
    const int total = g_plcount;

    for (int i = blockIdx.x * blockDim.x + threadIdx.x; i < total;
         i += gridDim.x * blockDim.x) {
        const int2 e = g_poslist[i];
        const int midx = e.x;
        const int matched = e.y;
        g_matched[midx] = 0;                       // self-clean for next run
        const int b = midx / NANCH;
        const int n = midx - b * NANCH;

        const float4 a = anchor_from_idx(n);
        const float aw = a.z - a.x, ah = a.w - a.y;
        const float acx = a.x + 0.5f * aw, acy = a.y + 0.5f * ah;
        const float4 rt = __ldg(&gt_boxes[b * MGT + matched]);

        const float4* rp = (const float4*)(reg_preds + ((size_t)b * NANCH + n) * 4 * NBINS);
        const float rts[4] = { rt.x, rt.y, rt.z, rt.w };
        float delta[4];
#pragma unroll
        for (int s = 0; s < 4; s++) {
            float l[16];
#pragma unroll
            for (int v = 0; v < 4; v++) {
                const float4 lv = __ldg(&rp[s * 4 + v]);
                l[v * 4 + 0] = lv.x; l[v * 4 + 1] = lv.y;
                l[v * 4 + 2] = lv.z; l[v * 4 + 3] = lv.w;
            }
            float mx = l[0];
#pragma unroll
            for (int k = 1; k < 16; k++) mx = fmaxf(mx, l[k]);

            const float ts = rts[s] * 15.f;
            int li = (int)ts; li = max(0, min(li, 14));
            const int ri = li + 1;
            const float wr = ts - (float)li, wl = 1.f - wr;

            float se = 0.f, ne = 0.f, lli = 0.f, lri = 0.f;
#pragma unroll
            for (int k = 0; k < 16; k++) {
                const float ek = expf(l[k] - mx);
                se += ek; ne += ek * (float)k;
                if (k == li) lli = l[k];
                if (k == ri) lri = l[k];
            }
            const float lz = mx + logf(se);
            dfl += -(wl * (lli - lz) + wr * (lri - lz));
            delta[s] = ne / (se * 15.f);
        }
        const float pcx = delta[0] * aw + acx;
        const float pcy = delta[1] * ah + acy;
        const float pw = expf(delta[2]) * aw;
        const float ph = expf(delta[3]) * ah;
        const float px1 = pcx - 0.5f * pw, py1 = pcy - 0.5f * ph;
        const float px2 = pcx + 0.5f * pw, py2 = pcy + 0.5f * ph;
        const float lx = fmaxf(px1, rt.x), ly = fmaxf(py1, rt.y);
        const float rx = fminf(px2, rt.z), ry = fminf(py2, rt.w);
        const float iw = fmaxf(rx - lx, 0.f), ih = fmaxf(ry - ly, 0.f);
        const float inter = iw * ih;
        const float pa = (px2 - px1) * (py2 - py1);
        const float ga = (rt.z - rt.x) * (rt.w - rt.y);
        const float uni = pa + ga - inter;
        const float iou = inter / fmaxf(uni, 1e-9f);
        const float ex1 = fminf(px1, rt.x), ey1 = fminf(py1, rt.y);
        const float ex2 = fmaxf(px2, rt.z), ey2 = fmaxf(py2, rt.w);
        const float ew = fmaxf(ex2 - ex1, 0.f), eh = fmaxf(ey2 - ey1, 0.f);
        const float enc = ew * eh;
        const float gv = iou - (enc - uni) / fmaxf(enc, 1e-9f);
        giou_l += 1.f - gv;
    }

    // block reduction
    const int lane = threadIdx.x & 31;
    const int warp = threadIdx.x >> 5;
#pragma unroll
    for (int off = 16; off > 0; off >>= 1) {
        dfl    += __shfl_xor_sync(0xffffffffu, dfl,    off);
        giou_l += __shfl_xor_sync(0xffffffffu, giou_l, off);
    }
    __shared__ float rd[8], rg[8];
    if (lane == 0) { rd[warp] = dfl; rg[warp] = giou_l; }
    __syncthreads();
    if (threadIdx.x == 0) {
        float dd = 0.f, gg = 0.f;
#pragma unroll
        for (int wi = 0; wi < REG_BLK / 32; wi++) { dd += rd[wi]; gg += rg[wi]; }
        if (dd != 0.f) atomicAdd(&g_dfl,  (double)dd);
        if (gg != 0.f) atomicAdd(&g_giou, (double)gg);
        __threadfence();
        const unsigned int ticket = atomicAdd(&g_count, 1u);
        if (ticket == REG_BLOCKS - 1) {
            const int pos = *((volatile int*)&g_pos);
            const double sq = *((volatile double*)&g_qfl);
            const double sd = *((volatile double*)&g_dfl);
            const double sg = *((volatile double*)&g_giou);
            const double npc = (double)max(pos, 1);
            const double qv = sq / npc;
            double df = sd / (double)max(4 * pos, 1);
            df = fmin(fmax(df, 0.0), 1.0);
            const double gi = sg / npc;
            out[0] = (float)(qv + df + gi);
            out[1] = (float)qv;
            out[2] = (float)df;
            out[3] = (float)gi;
            g_qfl = 0.0; g_dfl = 0.0; g_giou = 0.0; g_pos = 0; g_plcount = 0;
            __threadfence();
            g_count = 0u;
        }
    }
}

extern "C" void kernel_launch(void* const* d_in, const int* in_sizes, int n_in,
                              void* d_out, int out_size) {
    const float*  cls_preds = (const float*)d_in[0];
    const float*  reg_preds = (const float*)d_in[1];
    const float4* gt_boxes  = (const float4*)d_in[3];
    const int*    gt_labels = (const int*)d_in[4];
    float* out = (float*)d_out;

    match_kernel<<<128, 128>>>(gt_boxes);
    dim3 grid(QFL_GX, BATCH);
    qfl_kernel<<<grid, QFL_BLK>>>(cls_preds, gt_boxes, gt_labels);
    reg_kernel<<<REG_BLOCKS, REG_BLK>>>(reg_preds, gt_boxes, out);
}

// round 13
// speedup vs baseline: 1.1885x; 1.1885x over previous
#include <cuda_runtime.h>
#include <math.h>

#define NCLS   20
#define NBINS  16
#define NANCH  21824
#define BATCH  16
#define MGT    32
#define NGT    (BATCH*MGT)

#define LOSS_BLK   256
#define ANCH_PER_BLK (LOSS_BLK * 2)                        // 512
#define LOSS_GX    ((NANCH + ANCH_PER_BLK - 1) / ANCH_PER_BLK)  // 43
#define NBLOCKS    (LOSS_GX * BATCH)                       // 688

// global accumulators / scratch (no device mallocs allowed)
__device__ double g_qfl, g_dfl, g_giou;
__device__ int    g_pos;
__device__ unsigned int g_count;                 // ticket; self-resetting
__device__ int    g_matched[BATCH * NANCH];      // 0 = none, else m+1; self-clearing

// analytic anchor decode: bit-exact vs reference (validated by R12 rel_err)
__device__ __forceinline__ float4 anchor_from_idx(const int n) {
    const int l = (n >= 16384) + (n >= 20480) + (n >= 21504) + (n >= 21760);
    const int offs = (65536 - (65536 >> (2 * l))) / 3;
    const int shift = 7 - l;
    const int r = n - offs;
    const int iy = r >> shift;
    const int ix = r - (iy << shift);
    const float s = (float)(8 << l);
    const float cx = (ix + 0.5f) * s;
    const float cy = (iy + 0.5f) * s;
    const float half = 2.0f * s;
    return make_float4(cx - half, cy - half, cx + half, cy + half);
}

// ---------------------------------------------------------------------------
// Warp-cooperative ATSS threshold (R7-validated, bit-identical thresholds).
// ---------------------------------------------------------------------------
__device__ __forceinline__ float atss_threshold(const float4 gt, const int lane) {
    const float gcx = 0.5f * (gt.x + gt.z);
    const float gcy = 0.5f * (gt.y + gt.w);

    float cd[4]; int ci[4];
#pragma unroll
    for (int j = 0; j < 4; j++) {
        const int c = lane + 32 * j;
        float nrm = 3.4e38f; int idx = 0x7fffffff;
        if (c < 125) {
            const int l   = c / 25;
            const int rem = c - 25 * l;
            const int dy  = rem / 5;
            const int dx  = rem - 5 * dy;
            const int   n    = 128 >> l;
            const float s    = (float)(8 << l);
            const int   offs = (65536 - (65536 >> (2 * l))) / 3;
            const int jcx = (int)floorf(gcx / s);
            const int jcy = (int)floorf(gcy / s);
            const int lx0 = min(max(jcx - 2, 0), n - 5);
            const int ly0 = min(max(jcy - 2, 0), n - 5);
            const int ix = lx0 + dx;
            const int iy = ly0 + dy;
            const float cx = (ix + 0.5f) * s;
            const float cy = (iy + 0.5f) * s;
            const float ddx = cx - gcx;
            const float ddy = cy - gcy;
            const float ddy2 = __fmul_rn(ddy, ddy);
            nrm = sqrtf(__fadd_rn(__fmul_rn(ddx, ddx), ddy2));
            idx = offs + iy * n + ix;
        }
        cd[j] = nrm; ci[j] = idx;
    }

    int my_win = 0;
#pragma unroll
    for (int r = 0; r < 9; r++) {
        float bd = cd[0]; int bi = ci[0]; int bs = 0;
#pragma unroll
        for (int k = 1; k < 4; k++) {
            const bool lt = (cd[k] < bd) || (cd[k] == bd && ci[k] < bi);
            if (lt) { bd = cd[k]; bi = ci[k]; bs = k; }
        }
        float wd = bd; int wi = bi;
#pragma unroll
        for (int off = 16; off > 0; off >>= 1) {
            const float od = __shfl_xor_sync(0xffffffffu, wd, off);
            const int   oi = __shfl_xor_sync(0xffffffffu, wi, off);
            if (od < wd || (od == wd && oi < wi)) { wd = od; wi = oi; }
        }
        if (lane == r) my_win = wi;
        if (bi == wi) {
#pragma unroll
            for (int k = 0; k < 4; k++)
                if (k == bs) { cd[k] = 3.4e38f; ci[k] = 0x7fffffff; }
        }
    }

    const float area_g = (gt.z - gt.x) * (gt.w - gt.y);
    float iou = 0.f;
    if (lane < 9) {
        const float4 ab = anchor_from_idx(my_win);
        const float area_a = (ab.z - ab.x) * (ab.w - ab.y);
        const float lx = fmaxf(ab.x, gt.x), ly = fmaxf(ab.y, gt.y);
        const float rx = fminf(ab.z, gt.z), ry = fminf(ab.w, gt.w);
        const float iw = fmaxf(rx - lx, 0.f), ih = fmaxf(ry - ly, 0.f);
        const float inter = iw * ih;
        const float uni = area_a + area_g - inter;
        iou = inter / fmaxf(uni, 1e-9f);
    }

    float v[9];
#pragma unroll
    for (int k = 0; k < 9; k++) v[k] = __shfl_sync(0xffffffffu, iou, k);
    float sum = 0.f;
#pragma unroll
    for (int k = 0; k < 9; k++) sum += v[k];
    const float mean = sum / 9.0f;
    float vs = 0.f;
#pragma unroll
    for (int k = 0; k < 9; k++) { const float t = v[k] - mean; vs += t * t; }
    return mean + sqrtf(vs / 8.0f);
}

// ---------------------------------------------------------------------------
// Phase A: one WARP per GT: threshold + scatter matches (R10-validated).
// ---------------------------------------------------------------------------
__global__ void match_kernel(const float4* __restrict__ gt_boxes) {
    const int warp = threadIdx.x >> 5;
    const int lane = threadIdx.x & 31;
    const int g = blockIdx.x * 4 + warp;
    if (g >= NGT) return;

    const float4 gt = __ldg(&gt_boxes[g]);
    const float thr = atss_threshold(gt, lane);

    const int b = g >> 5;
    const int m = g & 31;
    int* mslice = g_matched + b * NANCH;
    const float area_g = (gt.z - gt.x) * (gt.w - gt.y);

#pragma unroll
    for (int l = 0; l < 5; l++) {
        const int   n    = 128 >> l;
        const float s    = (float)(8 << l);
        const float half = 2.0f * s;
        const int   offs = (65536 - (65536 >> (2 * l))) / 3;
        const int ix0 = max(0,     (int)floorf(gt.x / s - 0.5f) - 1);
        const int ix1 = min(n - 1, (int)ceilf (gt.z / s - 0.5f) + 1);
        const int iy0 = max(0,     (int)floorf(gt.y / s - 0.5f) - 1);
        const int iy1 = min(n - 1, (int)ceilf (gt.w / s - 0.5f) + 1);
        const int W = ix1 - ix0 + 1;
        const int H = iy1 - iy0 + 1;
        const int tot = W * H;
        for (int t = lane; t < tot; t += 32) {
            const int ty = t / W;
            const int iy = iy0 + ty;
            const int ix = ix0 + (t - ty * W);
            const float cx = (ix + 0.5f) * s;
            const float cy = (iy + 0.5f) * s;
            const bool inside = (cx >= gt.x) && (cx <= gt.z) &&
                                (cy >= gt.y) && (cy <= gt.w);
            if (inside) {
                const float ax = cx - half, ay = cy - half;
                const float az = cx + half, aw = cy + half;
                const float area_a = (az - ax) * (aw - ay);
                const float lx = fmaxf(ax, gt.x), ly = fmaxf(ay, gt.y);
                const float rx = fminf(az, gt.z), ry = fminf(aw, gt.w);
                const float iw = fmaxf(rx - lx, 0.f), ih = fmaxf(ry - ly, 0.f);
                const float inter = iw * ih;
                const float uni = area_a + area_g - inter;
                if (inter >= thr * uni)
                    atomicMax(&mslice[offs + iy * n + ix], m + 1);
            }
        }
    }
}

// ---------------------------------------------------------------------------
// Phase B: fused loss, TWO anchors per thread (n0 = base+tid, n1 = n0+256).
// Two independent QFL streams give 2x MLP/ILP to hide load + MUFU latency.
// Positives-only DFL/GIoU per anchor; ticket finalize (self-resetting).
// ---------------------------------------------------------------------------
__global__ void loss_kernel(const float* __restrict__ cls_preds,
                            const float* __restrict__ reg_preds,
                            const float4* __restrict__ gt_boxes,
                            const int* __restrict__ gt_labels,
                            float* __restrict__ out) {
    __shared__ float4 sGT[MGT];
    __shared__ float  sArea[MGT];
    __shared__ int    sLab[MGT];
    const int b = blockIdx.y;
    if (threadIdx.x < MGT) {
        const float4 gbx = gt_boxes[b * MGT + threadIdx.x];
        sGT[threadIdx.x]   = gbx;
        sArea[threadIdx.x] = (gbx.z - gbx.x) * (gbx.w - gbx.y);
        sLab[threadIdx.x]  = gt_labels[b * MGT + threadIdx.x];
    }
    __syncthreads();

    float qfl = 0.f, dfl = 0.f, giou_l = 0.f;
    int posi = 0;

    int   na[2];
    bool  valid[2], posa[2];
    int   mata[2], clsa[2];
    float ita[2];
    na[0] = blockIdx.x * ANCH_PER_BLK + threadIdx.x;
    na[1] = na[0] + LOSS_BLK;

#pragma unroll
    for (int a = 0; a < 2; a++) {
        const int n = na[a];
        valid[a] = n < NANCH;
        int mm = 0;
        if (valid[a]) mm = g_matched[b * NANCH + n];
        posa[a] = valid[a] && (mm > 0);
        if (posa[a]) g_matched[b * NANCH + n] = 0;      // self-clean
        mata[a] = posa[a] ? (mm - 1) : 0;
        clsa[a] = posa[a] ? sLab[mata[a]] : 0;
        float it = 0.f;
        if (posa[a]) {
            const float4 ab = anchor_from_idx(n);
            const float area_a = (ab.z - ab.x) * (ab.w - ab.y);
            const float4 gbx = sGT[mata[a]];
            const float lx = fmaxf(ab.x, gbx.x), ly = fmaxf(ab.y, gbx.y);
            const float rx = fminf(ab.z, gbx.z), ry = fminf(ab.w, gbx.w);
            const float iw = fmaxf(rx - lx, 0.f), ih = fmaxf(ry - ly, 0.f);
            const float inter = iw * ih;
            const float uni = area_a + sArea[mata[a]] - inter;
            it = inter / fmaxf(uni, 1e-9f);
        }
        ita[a] = it;
        posi += posa[a] ? 1 : 0;
    }

    // ---- QFL: two interleaved streams (fast-math, R5-validated math) ----
    {
        const float4* cp0 = (const float4*)(cls_preds + ((size_t)b * NANCH + na[0]) * NCLS);
        const float4* cp1 = (const float4*)(cls_preds + ((size_t)b * NANCH + na[1]) * NCLS);
#pragma unroll
        for (int v = 0; v < 5; v++) {
            float4 xv0 = make_float4(0.f, 0.f, 0.f, 0.f);
            float4 xv1 = make_float4(0.f, 0.f, 0.f, 0.f);
            if (valid[0]) xv0 = __ldg(&cp0[v]);
            if (valid[1]) xv1 = __ldg(&cp1[v]);
            const float xs0[4] = { xv0.x, xv0.y, xv0.z, xv0.w };
            const float xs1[4] = { xv1.x, xv1.y, xv1.z, xv1.w };
#pragma unroll
            for (int j = 0; j < 4; j++) {
                const int c = v * 4 + j;
                // stream 0
                {
                    const float x = xs0[j];
                    const bool tpos = (c == clsa[0]);
                    const float e = __expf(-fabsf(x));
                    const float sp = __logf(1.0f + e);
                    const float r = __fdividef(1.0f, 1.0f + e);
                    const float psig = (x >= 0.f) ? r : (1.0f - r);
                    const float pt = tpos ? psig : (1.0f - psig);
                    const float bce = fmaxf(x, 0.f) - (tpos ? x : 0.f) + sp;
                    const float w = fmaf(ita[0], 1.0f - 2.0f * pt, pt);
                    if (valid[0]) qfl += w * w * bce;
                }
                // stream 1
                {
                    const float x = xs1[j];
                    const bool tpos = (c == clsa[1]);
                    const float e = __expf(-fabsf(x));
                    const float sp = __logf(1.0f + e);
                    const float r = __fdividef(1.0f, 1.0f + e);
                    const float psig = (x >= 0.f) ? r : (1.0f - r);
                    const float pt = tpos ? psig : (1.0f - psig);
                    const float bce = fmaxf(x, 0.f) - (tpos ? x : 0.f) + sp;
                    const float w = fmaf(ita[1], 1.0f - 2.0f * pt, pt);
                    if (valid[1]) qfl += w * w * bce;
                }
            }
        }
    }

    // ---- DFL + decode + GIoU: positives only (validated accurate math) ----
#pragma unroll
    for (int a = 0; a < 2; a++) {
        if (posa[a]) {
            const int n = na[a];
            const float4 ab = anchor_from_idx(n);
            const float aw = ab.z - ab.x, ah = ab.w - ab.y;
            const float acx = ab.x + 0.5f * aw, acy = ab.y + 0.5f * ah;
            const float4 rt = sGT[mata[a]];
            const float4* rp = (const float4*)(reg_preds + ((size_t)b * NANCH + n) * 4 * NBINS);
            const float rts[4] = { rt.x, rt.y, rt.z, rt.w };
            float delta[4];
#pragma unroll
            for (int s = 0; s < 4; s++) {
                float l[16];
#pragma unroll
                for (int v = 0; v < 4; v++) {
                    const float4 lv = __ldg(&rp[s * 4 + v]);
                    l[v * 4 + 0] = lv.x; l[v * 4 + 1] = lv.y;
                    l[v * 4 + 2] = lv.z; l[v * 4 + 3] = lv.w;
                }
                float mx = l[0];
#pragma unroll
                for (int k = 1; k < 16; k++) mx = fmaxf(mx, l[k]);

                const float ts = rts[s] * 15.f;
                int li = (int)ts; li = max(0, min(li, 14));
                const int ri = li + 1;
                const float wr = ts - (float)li, wl = 1.f - wr;

                float se = 0.f, ne = 0.f, lli = 0.f, lri = 0.f;
#pragma unroll
                for (int k = 0; k < 16; k++) {
                    const float ek = expf(l[k] - mx);
                    se += ek; ne += ek * (float)k;
                    if (k == li) lli = l[k];
                    if (k == ri) lri = l[k];
                }
                const float lz = mx + logf(se);
                dfl += -(wl * (lli - lz) + wr * (lri - lz));
                delta[s] = ne / (se * 15.f);
            }
            const float pcx = delta[0] * aw + acx;
            const float pcy = delta[1] * ah + acy;
            const float pw = expf(delta[2]) * aw;
            const float ph = expf(delta[3]) * ah;
            const float px1 = pcx - 0.5f * pw, py1 = pcy - 0.5f * ph;
            const float px2 = pcx + 0.5f * pw, py2 = pcy + 0.5f * ph;
            const float lx = fmaxf(px1, rt.x), ly = fmaxf(py1, rt.y);
            const float rx = fminf(px2, rt.z), ry = fminf(py2, rt.w);
            const float iw = fmaxf(rx - lx, 0.f), ih = fmaxf(ry - ly, 0.f);
            const float inter = iw * ih;
            const float pa = (px2 - px1) * (py2 - py1);
            const float ga = (rt.z - rt.x) * (rt.w - rt.y);
            const float uni = pa + ga - inter;
            const float iou = inter / fmaxf(uni, 1e-9f);
            const float ex1 = fminf(px1, rt.x), ey1 = fminf(py1, rt.y);
            const float ex2 = fmaxf(px2, rt.z), ey2 = fmaxf(py2, rt.w);
            const float ew = fmaxf(ex2 - ex1, 0.f), eh = fmaxf(ey2 - ey1, 0.f);
            const float enc = ew * eh;
            const float gv = iou - (enc - uni) / fmaxf(enc, 1e-9f);
            giou_l += 1.f - gv;
        }
    }

    // ---- reduction: warp -> block -> global double atomics ----
#pragma unroll
    for (int off = 16; off > 0; off >>= 1) {
        qfl    += __shfl_xor_sync(0xffffffffu, qfl,    off);
        dfl    += __shfl_xor_sync(0xffffffffu, dfl,    off);
        giou_l += __shfl_xor_sync(0xffffffffu, giou_l, off);
        posi   += __shfl_xor_sync(0xffffffffu, posi,   off);
    }
    __shared__ float rq[8], rd[8], rg[8];
    __shared__ int   rp_[8];
    const int warp = threadIdx.x >> 5;
    const int lane = threadIdx.x & 31;
    if (lane == 0) { rq[warp] = qfl; rd[warp] = dfl; rg[warp] = giou_l; rp_[warp] = posi; }
    __syncthreads();
    if (threadIdx.x == 0) {
        float q = 0.f, dd = 0.f, gg = 0.f; int pp = 0;
#pragma unroll
        for (int wi = 0; wi < LOSS_BLK / 32; wi++) {
            q += rq[wi]; dd += rd[wi]; gg += rg[wi]; pp += rp_[wi];
        }
        if (q  != 0.f) atomicAdd(&g_qfl,  (double)q);
        if (dd != 0.f) atomicAdd(&g_dfl,  (double)dd);
        if (gg != 0.f) atomicAdd(&g_giou, (double)gg);
        if (pp != 0)   atomicAdd(&g_pos,  pp);
        __threadfence();
        const unsigned int ticket = atomicAdd(&g_count, 1u);
        if (ticket == NBLOCKS - 1) {
            const int pos = *((volatile int*)&g_pos);
            const double sq = *((volatile double*)&g_qfl);
            const double sd = *((volatile double*)&g_dfl);
            const double sg = *((volatile double*)&g_giou);
            const double npc = (double)max(pos, 1);
            const double qv = sq / npc;
            double df = sd / (double)max(4 * pos, 1);
            df = fmin(fmax(df, 0.0), 1.0);
            const double gi = sg / npc;
            out[0] = (float)(qv + df + gi);
            out[1] = (float)qv;
            out[2] = (float)df;
            out[3] = (float)gi;
            g_qfl = 0.0; g_dfl = 0.0; g_giou = 0.0; g_pos = 0;
            __threadfence();
            g_count = 0u;
        }
    }
}

extern "C" void kernel_launch(void* const* d_in, const int* in_sizes, int n_in,
                              void* d_out, int out_size) {
    const float*  cls_preds = (const float*)d_in[0];
    const float*  reg_preds = (const float*)d_in[1];
    const float4* gt_boxes  = (const float4*)d_in[3];
    const int*    gt_labels = (const int*)d_in[4];
    float* out = (float*)d_out;

    match_kernel<<<128, 128>>>(gt_boxes);
    dim3 grid(LOSS_GX, BATCH);
    loss_kernel<<<grid, LOSS_BLK>>>(cls_preds, reg_preds, gt_boxes, gt_labels, out);
}

// round 15
// speedup vs baseline: 1.3086x; 1.1011x over previous
#include <cuda_runtime.h>
#include <math.h>

#define NCLS   20
#define NBINS  16
#define NANCH  21824
#define BATCH  16
#define MGT    32
#define NGT    (BATCH*MGT)

#define LOSS_BLK   256
#define LOSS_GX    ((NANCH + LOSS_BLK - 1) / LOSS_BLK)   // 86
#define NBLOCKS    (LOSS_GX * BATCH)                      // 1376

// global accumulators / scratch (no device mallocs allowed)
__device__ double g_qfl, g_dfl, g_giou;
__device__ int    g_pos;
__device__ unsigned int g_count;                 // ticket; self-resetting
__device__ int    g_matched[BATCH * NANCH];      // 0 = none, else m+1; self-clearing

// analytic anchor decode: bit-exact vs reference (validated by R12/R13 rel_err)
__device__ __forceinline__ float4 anchor_from_idx(const int n) {
    const int l = (n >= 16384) + (n >= 20480) + (n >= 21504) + (n >= 21760);
    const int offs = (65536 - (65536 >> (2 * l))) / 3;
    const int shift = 7 - l;
    const int r = n - offs;
    const int iy = r >> shift;
    const int ix = r - (iy << shift);
    const float s = (float)(8 << l);
    const float cx = (ix + 0.5f) * s;
    const float cy = (iy + 0.5f) * s;
    const float half = 2.0f * s;
    return make_float4(cx - half, cy - half, cx + half, cy + half);
}

// ---------------------------------------------------------------------------
// Warp-cooperative ATSS threshold (R7-validated, bit-identical thresholds).
// ---------------------------------------------------------------------------
__device__ __forceinline__ float atss_threshold(const float4 gt, const int lane) {
    const float gcx = 0.5f * (gt.x + gt.z);
    const float gcy = 0.5f * (gt.y + gt.w);

    float cd[4]; int ci[4];
#pragma unroll
    for (int j = 0; j < 4; j++) {
        const int c = lane + 32 * j;
        float nrm = 3.4e38f; int idx = 0x7fffffff;
        if (c < 125) {
            const int l   = c / 25;
            const int rem = c - 25 * l;
            const int dy  = rem / 5;
            const int dx  = rem - 5 * dy;
            const int   n    = 128 >> l;
            const float s    = (float)(8 << l);
            const int   offs = (65536 - (65536 >> (2 * l))) / 3;
            const int jcx = (int)floorf(gcx / s);
            const int jcy = (int)floorf(gcy / s);
            const int lx0 = min(max(jcx - 2, 0), n - 5);
            const int ly0 = min(max(jcy - 2, 0), n - 5);
            const int ix = lx0 + dx;
            const int iy = ly0 + dy;
            const float cx = (ix + 0.5f) * s;
            const float cy = (iy + 0.5f) * s;
            const float ddx = cx - gcx;
            const float ddy = cy - gcy;
            const float ddy2 = __fmul_rn(ddy, ddy);
            nrm = sqrtf(__fadd_rn(__fmul_rn(ddx, ddx), ddy2));
            idx = offs + iy * n + ix;
        }
        cd[j] = nrm; ci[j] = idx;
    }

    int my_win = 0;
#pragma unroll
    for (int r = 0; r < 9; r++) {
        float bd = cd[0]; int bi = ci[0]; int bs = 0;
#pragma unroll
        for (int k = 1; k < 4; k++) {
            const bool lt = (cd[k] < bd) || (cd[k] == bd && ci[k] < bi);
            if (lt) { bd = cd[k]; bi = ci[k]; bs = k; }
        }
        float wd = bd; int wi = bi;
#pragma unroll
        for (int off = 16; off > 0; off >>= 1) {
            const float od = __shfl_xor_sync(0xffffffffu, wd, off);
            const int   oi = __shfl_xor_sync(0xffffffffu, wi, off);
            if (od < wd || (od == wd && oi < wi)) { wd = od; wi = oi; }
        }
        if (lane == r) my_win = wi;
        if (bi == wi) {
#pragma unroll
            for (int k = 0; k < 4; k++)
                if (k == bs) { cd[k] = 3.4e38f; ci[k] = 0x7fffffff; }
        }
    }

    const float area_g = (gt.z - gt.x) * (gt.w - gt.y);
    float iou = 0.f;
    if (lane < 9) {
        const float4 ab = anchor_from_idx(my_win);
        const float area_a = (ab.z - ab.x) * (ab.w - ab.y);
        const float lx = fmaxf(ab.x, gt.x), ly = fmaxf(ab.y, gt.y);
        const float rx = fminf(ab.z, gt.z), ry = fminf(ab.w, gt.w);
        const float iw = fmaxf(rx - lx, 0.f), ih = fmaxf(ry - ly, 0.f);
        const float inter = iw * ih;
        const float uni = area_a + area_g - inter;
        iou = inter / fmaxf(uni, 1e-9f);
    }

    float v[9];
#pragma unroll
    for (int k = 0; k < 9; k++) v[k] = __shfl_sync(0xffffffffu, iou, k);
    float sum = 0.f;
#pragma unroll
    for (int k = 0; k < 9; k++) sum += v[k];
    const float mean = sum / 9.0f;
    float vs = 0.f;
#pragma unroll
    for (int k = 0; k < 9; k++) { const float t = v[k] - mean; vs += t * t; }
    return mean + sqrtf(vs / 8.0f);
}

// ---------------------------------------------------------------------------
// Phase A: one WARP per GT: threshold + scatter matches (R10-validated).
// ---------------------------------------------------------------------------
__global__ void match_kernel(const float4* __restrict__ gt_boxes) {
    const int warp = threadIdx.x >> 5;
    const int lane = threadIdx.x & 31;
    const int g = blockIdx.x * 4 + warp;
    if (g >= NGT) return;

    const float4 gt = __ldg(&gt_boxes[g]);
    const float thr = atss_threshold(gt, lane);

    const int b = g >> 5;
    const int m = g & 31;
    int* mslice = g_matched + b * NANCH;
    const float area_g = (gt.z - gt.x) * (gt.w - gt.y);

#pragma unroll
    for (int l = 0; l < 5; l++) {
        const int   n    = 128 >> l;
        const float s    = (float)(8 << l);
        const float half = 2.0f * s;
        const int   offs = (65536 - (65536 >> (2 * l))) / 3;
        const int ix0 = max(0,     (int)floorf(gt.x / s - 0.5f) - 1);
        const int ix1 = min(n - 1, (int)ceilf (gt.z / s - 0.5f) + 1);
        const int iy0 = max(0,     (int)floorf(gt.y / s - 0.5f) - 1);
        const int iy1 = min(n - 1, (int)ceilf (gt.w / s - 0.5f) + 1);
        const int W = ix1 - ix0 + 1;
        const int H = iy1 - iy0 + 1;
        const int tot = W * H;
        for (int t = lane; t < tot; t += 32) {
            const int ty = t / W;
            const int iy = iy0 + ty;
            const int ix = ix0 + (t - ty * W);
            const float cx = (ix + 0.5f) * s;
            const float cy = (iy + 0.5f) * s;
            const bool inside = (cx >= gt.x) && (cx <= gt.z) &&
                                (cy >= gt.y) && (cy <= gt.w);
            if (inside) {
                const float ax = cx - half, ay = cy - half;
                const float az = cx + half, aw = cy + half;
                const float area_a = (az - ax) * (aw - ay);
                const float lx = fmaxf(ax, gt.x), ly = fmaxf(ay, gt.y);
                const float rx = fminf(az, gt.z), ry = fminf(aw, gt.w);
                const float iw = fmaxf(rx - lx, 0.f), ih = fmaxf(ry - ly, 0.f);
                const float inter = iw * ih;
                const float uni = area_a + area_g - inter;
                if (inter >= thr * uni)
                    atomicMax(&mslice[offs + iy * n + ix], m + 1);
            }
        }
    }
}

// ---------------------------------------------------------------------------
// Phase B: fused loss (R10 structure). QFL restructured: branch-free
// all-negative sum per class (pt = r = 1/(1+e^x), bce = log(1+e^x)), plus
// ONE per-anchor correction at the target class:
//   QFL_pos(x) - QFL_neg(x),  bce_pos = log(1+e^x) - x.
// Positives-only DFL/GIoU; ticket finalize (self-resetting).
// ---------------------------------------------------------------------------
__global__ void loss_kernel(const float* __restrict__ cls_preds,
                            const float* __restrict__ reg_preds,
                            const float4* __restrict__ gt_boxes,
                            const int* __restrict__ gt_labels,
                            float* __restrict__ out) {
    __shared__ float4 sGT[MGT];
    __shared__ float  sArea[MGT];
    __shared__ int    sLab[MGT];
    const int b = blockIdx.y;
    if (threadIdx.x < MGT) {
        const float4 gbx = gt_boxes[b * MGT + threadIdx.x];
        sGT[threadIdx.x]   = gbx;
        sArea[threadIdx.x] = (gbx.z - gbx.x) * (gbx.w - gbx.y);
        sLab[threadIdx.x]  = gt_labels[b * MGT + threadIdx.x];
    }
    __syncthreads();

    const int n = blockIdx.x * blockDim.x + threadIdx.x;
    float qfl = 0.f, dfl = 0.f, giou_l = 0.f;
    int posi = 0;

    if (n < NANCH) {
        const int midx = b * NANCH + n;
        const int mm = g_matched[midx];
        const bool pos = mm > 0;
        if (pos) g_matched[midx] = 0;              // self-clean for next run
        const int matched = pos ? (mm - 1) : 0;
        const int cls_t = pos ? sLab[matched] : 0;

        const float4 a = anchor_from_idx(n);
        const float aw = a.z - a.x, ah = a.w - a.y;
        const float acx = a.x + 0.5f * aw, acy = a.y + 0.5f * ah;

        float it = 0.f;
        if (pos) {
            const float area_a = aw * ah;
            const float4 gbx = sGT[matched];
            const float lx = fmaxf(a.x, gbx.x), ly = fmaxf(a.y, gbx.y);
            const float rx = fminf(a.z, gbx.z), ry = fminf(a.w, gbx.w);
            const float iw = fmaxf(rx - lx, 0.f), ih = fmaxf(ry - ly, 0.f);
            const float inter = iw * ih;
            const float uni = area_a + sArea[matched] - inter;
            it = inter / fmaxf(uni, 1e-9f);
        }
        posi = pos ? 1 : 0;
        const float4 rt = pos ? sGT[matched] : make_float4(0.f, 0.f, 0.f, 0.f);

        // ---- QFL: uniform negative pass + single target-class correction ----
        {
            const float4* cp = (const float4*)(cls_preds + ((size_t)b * NANCH + n) * NCLS);
            float xsel = 0.f;
#pragma unroll
            for (int v = 0; v < 5; v++) {
                const float4 xv = __ldg(&cp[v]);
                const float xs[4] = { xv.x, xv.y, xv.z, xv.w };
#pragma unroll
                for (int j = 0; j < 4; j++) {
                    const int c = v * 4 + j;
                    const float x = xs[j];
                    const float e = __expf(x);                  // |x| small: no overflow
                    const float d = 1.0f + e;
                    const float sp = __logf(d);                 // bce (t=0)
                    const float r = __fdividef(1.0f, d);        // pt  (t=0) = 1 - sigmoid
                    const float w = fmaf(it, 1.0f - 2.0f * r, r);
                    qfl += (w * w) * sp;
                    if (c == cls_t) xsel = x;
                }
            }
            // correction at the target class (every anchor has exactly one)
            {
                const float e = __expf(xsel);
                const float d = 1.0f + e;
                const float sp = __logf(d);
                const float r = __fdividef(1.0f, d);
                // remove the negative-style term
                const float wn = fmaf(it, 1.0f - 2.0f * r, r);
                const float neg = (wn * wn) * sp;
                // add the positive-style term: pt = sigmoid = 1-r, bce = sp - x
                const float psig = 1.0f - r;
                const float wp = fmaf(it, 1.0f - 2.0f * psig, psig);
                const float posv = (wp * wp) * (sp - xsel);
                qfl += posv - neg;
            }
        }

        // ---- DFL + decode + GIoU: positives only (validated accurate math) ----
        if (pos) {
            const float4* rp = (const float4*)(reg_preds + ((size_t)b * NANCH + n) * 4 * NBINS);
            const float rts[4] = { rt.x, rt.y, rt.z, rt.w };
            float delta[4];
#pragma unroll
            for (int s = 0; s < 4; s++) {
                float l[16];
#pragma unroll
                for (int v = 0; v < 4; v++) {
                    const float4 lv = __ldg(&rp[s * 4 + v]);
                    l[v * 4 + 0] = lv.x; l[v * 4 + 1] = lv.y;
                    l[v * 4 + 2] = lv.z; l[v * 4 + 3] = lv.w;
                }
                float mx = l[0];
#pragma unroll
                for (int k = 1; k < 16; k++) mx = fmaxf(mx, l[k]);

                const float ts = rts[s] * 15.f;
                int li = (int)ts; li = max(0, min(li, 14));
                const int ri = li + 1;
                const float wr = ts - (float)li, wl = 1.f - wr;

                float se = 0.f, ne = 0.f, lli = 0.f, lri = 0.f;
#pragma unroll
                for (int k = 0; k < 16; k++) {
                    const float ek = expf(l[k] - mx);
                    se += ek; ne += ek * (float)k;
                    if (k == li) lli = l[k];
                    if (k == ri) lri = l[k];
                }
                const float lz = mx + logf(se);
                dfl += -(wl * (lli - lz) + wr * (lri - lz));
                delta[s] = ne / (se * 15.f);
            }
            const float pcx = delta[0] * aw + acx;
            const float pcy = delta[1] * ah + acy;
            const float pw = expf(delta[2]) * aw;
            const float ph = expf(delta[3]) * ah;
            const float px1 = pcx - 0.5f * pw, py1 = pcy - 0.5f * ph;
            const float px2 = pcx + 0.5f * pw, py2 = pcy + 0.5f * ph;
            const float lx = fmaxf(px1, rt.x), ly = fmaxf(py1, rt.y);
            const float rx = fminf(px2, rt.z), ry = fminf(py2, rt.w);
            const float iw = fmaxf(rx - lx, 0.f), ih = fmaxf(ry - ly, 0.f);
            const float inter = iw * ih;
            const float pa = (px2 - px1) * (py2 - py1);
            const float ga = (rt.z - rt.x) * (rt.w - rt.y);
            const float uni = pa + ga - inter;
            const float iou = inter / fmaxf(uni, 1e-9f);
            const float ex1 = fminf(px1, rt.x), ey1 = fminf(py1, rt.y);
            const float ex2 = fmaxf(px2, rt.z), ey2 = fmaxf(py2, rt.w);
            const float ew = fmaxf(ex2 - ex1, 0.f), eh = fmaxf(ey2 - ey1, 0.f);
            const float enc = ew * eh;
            const float gv = iou - (enc - uni) / fmaxf(enc, 1e-9f);
            giou_l = 1.f - gv;
        }
    }

    // ---- reduction: warp -> block -> global double atomics ----
#pragma unroll
    for (int off = 16; off > 0; off >>= 1) {
        qfl    += __shfl_xor_sync(0xffffffffu, qfl,    off);
        dfl    += __shfl_xor_sync(0xffffffffu, dfl,    off);
        giou_l += __shfl_xor_sync(0xffffffffu, giou_l, off);
        posi   += __shfl_xor_sync(0xffffffffu, posi,   off);
    }
    __shared__ float rq[8], rd[8], rg[8];
    __shared__ int   rp_[8];
    const int warp = threadIdx.x >> 5;
    const int lane = threadIdx.x & 31;
    if (lane == 0) { rq[warp] = qfl; rd[warp] = dfl; rg[warp] = giou_l; rp_[warp] = posi; }
    __syncthreads();
    if (threadIdx.x == 0) {
        float q = 0.f, dd = 0.f, gg = 0.f; int pp = 0;
#pragma unroll
        for (int wi = 0; wi < LOSS_BLK / 32; wi++) {
            q += rq[wi]; dd += rd[wi]; gg += rg[wi]; pp += rp_[wi];
        }
        if (q  != 0.f) atomicAdd(&g_qfl,  (double)q);
        if (dd != 0.f) atomicAdd(&g_dfl,  (double)dd);
        if (gg != 0.f) atomicAdd(&g_giou, (double)gg);
        if (pp != 0)   atomicAdd(&g_pos,  pp);
        __threadfence();
        const unsigned int ticket = atomicAdd(&g_count, 1u);
        if (ticket == NBLOCKS - 1) {
            const int pos = *((volatile int*)&g_pos);
            const double sq = *((volatile double*)&g_qfl);
            const double sd = *((volatile double*)&g_dfl);
            const double sg = *((volatile double*)&g_giou);
            const double npc = (double)max(pos, 1);
            const double qv = sq / npc;
            double df = sd / (double)max(4 * pos, 1);
            df = fmin(fmax(df, 0.0), 1.0);
            const double gi = sg / npc;
            out[0] = (float)(qv + df + gi);
            out[1] = (float)qv;
            out[2] = (float)df;
            out[3] = (float)gi;
            g_qfl = 0.0; g_dfl = 0.0; g_giou = 0.0; g_pos = 0;
            __threadfence();
            g_count = 0u;
        }
    }
}

extern "C" void kernel_launch(void* const* d_in, const int* in_sizes, int n_in,
                              void* d_out, int out_size) {
    const float*  cls_preds = (const float*)d_in[0];
    const float*  reg_preds = (const float*)d_in[1];
    const float4* gt_boxes  = (const float4*)d_in[3];
    const int*    gt_labels = (const int*)d_in[4];
    float* out = (float*)d_out;

    match_kernel<<<128, 128>>>(gt_boxes);
    dim3 grid(LOSS_GX, BATCH);
    loss_kernel<<<grid, LOSS_BLK>>>(cls_preds, reg_preds, gt_boxes, gt_labels, out);
}

// round 17
// speedup vs baseline: 1.4168x; 1.0827x over previous
#include <cuda_runtime.h>
#include <math.h>

#define NCLS   20
#define NBINS  16
#define NANCH  21824
#define BATCH  16
#define MGT    32
#define NGT    (BATCH*MGT)

#define LOSS_BLK   256
#define LOSS_GX    ((NANCH + LOSS_BLK - 1) / LOSS_BLK)   // 86
#define NBLOCKS    (LOSS_GX * BATCH)                      // 1376

// global accumulators / scratch (no device mallocs allowed)
__device__ double g_qfl, g_dfl, g_giou;
__device__ int    g_pos;
__device__ unsigned int g_count;                 // ticket; self-resetting
__device__ int    g_matched[BATCH * NANCH];      // 0 = none, else m+1; self-clearing

// analytic anchor decode: bit-exact vs reference (validated R12-R15)
__device__ __forceinline__ float4 anchor_from_idx(const int n) {
    const int l = (n >= 16384) + (n >= 20480) + (n >= 21504) + (n >= 21760);
    const int offs = (65536 - (65536 >> (2 * l))) / 3;
    const int shift = 7 - l;
    const int r = n - offs;
    const int iy = r >> shift;
    const int ix = r - (iy << shift);
    const float s = (float)(8 << l);
    const float cx = (ix + 0.5f) * s;
    const float cy = (iy + 0.5f) * s;
    const float half = 2.0f * s;
    return make_float4(cx - half, cy - half, cx + half, cy + half);
}

// ---------------------------------------------------------------------------
// Warp-cooperative ATSS threshold (R7-validated, bit-identical thresholds).
// Executed by ONE warp; returns thr on all lanes of that warp.
// ---------------------------------------------------------------------------
__device__ __forceinline__ float atss_threshold(const float4 gt, const int lane) {
    const float gcx = 0.5f * (gt.x + gt.z);
    const float gcy = 0.5f * (gt.y + gt.w);

    float cd[4]; int ci[4];
#pragma unroll
    for (int j = 0; j < 4; j++) {
        const int c = lane + 32 * j;
        float nrm = 3.4e38f; int idx = 0x7fffffff;
        if (c < 125) {
            const int l   = c / 25;
            const int rem = c - 25 * l;
            const int dy  = rem / 5;
            const int dx  = rem - 5 * dy;
            const int   n    = 128 >> l;
            const float s    = (float)(8 << l);
            const int   offs = (65536 - (65536 >> (2 * l))) / 3;
            const int jcx = (int)floorf(gcx / s);
            const int jcy = (int)floorf(gcy / s);
            const int lx0 = min(max(jcx - 2, 0), n - 5);
            const int ly0 = min(max(jcy - 2, 0), n - 5);
            const int ix = lx0 + dx;
            const int iy = ly0 + dy;
            const float cx = (ix + 0.5f) * s;
            const float cy = (iy + 0.5f) * s;
            const float ddx = cx - gcx;
            const float ddy = cy - gcy;
            const float ddy2 = __fmul_rn(ddy, ddy);
            nrm = sqrtf(__fadd_rn(__fmul_rn(ddx, ddx), ddy2));
            idx = offs + iy * n + ix;
        }
        cd[j] = nrm; ci[j] = idx;
    }

    int my_win = 0;
#pragma unroll
    for (int r = 0; r < 9; r++) {
        float bd = cd[0]; int bi = ci[0]; int bs = 0;
#pragma unroll
        for (int k = 1; k < 4; k++) {
            const bool lt = (cd[k] < bd) || (cd[k] == bd && ci[k] < bi);
            if (lt) { bd = cd[k]; bi = ci[k]; bs = k; }
        }
        float wd = bd; int wi = bi;
#pragma unroll
        for (int off = 16; off > 0; off >>= 1) {
            const float od = __shfl_xor_sync(0xffffffffu, wd, off);
            const int   oi = __shfl_xor_sync(0xffffffffu, wi, off);
            if (od < wd || (od == wd && oi < wi)) { wd = od; wi = oi; }
        }
        if (lane == r) my_win = wi;
        if (bi == wi) {
#pragma unroll
            for (int k = 0; k < 4; k++)
                if (k == bs) { cd[k] = 3.4e38f; ci[k] = 0x7fffffff; }
        }
    }

    const float area_g = (gt.z - gt.x) * (gt.w - gt.y);
    float iou = 0.f;
    if (lane < 9) {
        const float4 ab = anchor_from_idx(my_win);
        const float area_a = (ab.z - ab.x) * (ab.w - ab.y);
        const float lx = fmaxf(ab.x, gt.x), ly = fmaxf(ab.y, gt.y);
        const float rx = fminf(ab.z, gt.z), ry = fminf(ab.w, gt.w);
        const float iw = fmaxf(rx - lx, 0.f), ih = fmaxf(ry - ly, 0.f);
        const float inter = iw * ih;
        const float uni = area_a + area_g - inter;
        iou = inter / fmaxf(uni, 1e-9f);
    }

    float v[9];
#pragma unroll
    for (int k = 0; k < 9; k++) v[k] = __shfl_sync(0xffffffffu, iou, k);
    float sum = 0.f;
#pragma unroll
    for (int k = 0; k < 9; k++) sum += v[k];
    const float mean = sum / 9.0f;
    float vs = 0.f;
#pragma unroll
    for (int k = 0; k < 9; k++) { const float t = v[k] - mean; vs += t * t; }
    return mean + sqrtf(vs / 8.0f);
}

// ---------------------------------------------------------------------------
// Phase A: one BLOCK (128 threads) per GT. Warp 0 computes the threshold
// (validated warp routine), broadcasts via smem; all 128 threads share the
// scatter enumeration (same candidates / compares / atomicMax => identical
// matches to R10, 4x the scatter parallelism and 4x the blocks).
// ---------------------------------------------------------------------------
__global__ void match_kernel(const float4* __restrict__ gt_boxes) {
    __shared__ float sThr;
    const int g = blockIdx.x;                       // 0..511
    if (g == 0 && threadIdx.x == 0) {
        g_qfl = 0.0; g_dfl = 0.0; g_giou = 0.0; g_pos = 0;  // defensive
    }

    const float4 gt = __ldg(&gt_boxes[g]);
    if (threadIdx.x < 32) {
        const float t = atss_threshold(gt, threadIdx.x);
        if (threadIdx.x == 0) sThr = t;
    }
    __syncthreads();
    const float thr = sThr;

    const int b = g >> 5;
    const int m = g & 31;
    int* mslice = g_matched + b * NANCH;
    const float area_g = (gt.z - gt.x) * (gt.w - gt.y);

#pragma unroll
    for (int l = 0; l < 5; l++) {
        const int   n    = 128 >> l;
        const float s    = (float)(8 << l);
        const float half = 2.0f * s;
        const int   offs = (65536 - (65536 >> (2 * l))) / 3;
        const int ix0 = max(0,     (int)floorf(gt.x / s - 0.5f) - 1);
        const int ix1 = min(n - 1, (int)ceilf (gt.z / s - 0.5f) + 1);
        const int iy0 = max(0,     (int)floorf(gt.y / s - 0.5f) - 1);
        const int iy1 = min(n - 1, (int)ceilf (gt.w / s - 0.5f) + 1);
        const int W = ix1 - ix0 + 1;
        const int H = iy1 - iy0 + 1;
        const int tot = W * H;
        for (int t = threadIdx.x; t < tot; t += 128) {
            const int ty = t / W;
            const int iy = iy0 + ty;
            const int ix = ix0 + (t - ty * W);
            const float cx = (ix + 0.5f) * s;
            const float cy = (iy + 0.5f) * s;
            const bool inside = (cx >= gt.x) && (cx <= gt.z) &&
                                (cy >= gt.y) && (cy <= gt.w);
            if (inside) {
                const float ax = cx - half, ay = cy - half;
                const float az = cx + half, aw = cy + half;
                const float area_a = (az - ax) * (aw - ay);
                const float lx = fmaxf(ax, gt.x), ly = fmaxf(ay, gt.y);
                const float rx = fminf(az, gt.z), ry = fminf(aw, gt.w);
                const float iw = fmaxf(rx - lx, 0.f), ih = fmaxf(ry - ly, 0.f);
                const float inter = iw * ih;
                const float uni = area_a + area_g - inter;
                if (inter >= thr * uni)
                    atomicMax(&mslice[offs + iy * n + ix], m + 1);
            }
        }
    }
}

// ---------------------------------------------------------------------------
// Phase B: fused loss (R15 math, unchanged). __launch_bounds__(256, 6) caps
// registers (~42) to lift occupancy from 5 to 6 blocks/SM; any spill lands in
// the positives-only DFL path (~0.4% of threads).
// ---------------------------------------------------------------------------
__global__ void __launch_bounds__(LOSS_BLK, 6)
loss_kernel(const float* __restrict__ cls_preds,
            const float* __restrict__ reg_preds,
            const float4* __restrict__ gt_boxes,
            const int* __restrict__ gt_labels,
            float* __restrict__ out) {
    __shared__ float4 sGT[MGT];
    __shared__ float  sArea[MGT];
    __shared__ int    sLab[MGT];
    const int b = blockIdx.y;
    if (threadIdx.x < MGT) {
        const float4 gbx = gt_boxes[b * MGT + threadIdx.x];
        sGT[threadIdx.x]   = gbx;
        sArea[threadIdx.x] = (gbx.z - gbx.x) * (gbx.w - gbx.y);
        sLab[threadIdx.x]  = gt_labels[b * MGT + threadIdx.x];
    }
    __syncthreads();

    const int n = blockIdx.x * blockDim.x + threadIdx.x;
    float qfl = 0.f, dfl = 0.f, giou_l = 0.f;
    int posi = 0;

    if (n < NANCH) {
        const int midx = b * NANCH + n;
        const int mm = g_matched[midx];
        const bool pos = mm > 0;
        if (pos) g_matched[midx] = 0;              // self-clean for next run
        const int matched = pos ? (mm - 1) : 0;
        const int cls_t = pos ? sLab[matched] : 0;

        const float4 a = anchor_from_idx(n);
        const float aw = a.z - a.x, ah = a.w - a.y;
        const float acx = a.x + 0.5f * aw, acy = a.y + 0.5f * ah;

        float it = 0.f;
        if (pos) {
            const float area_a = aw * ah;
            const float4 gbx = sGT[matched];
            const float lx = fmaxf(a.x, gbx.x), ly = fmaxf(a.y, gbx.y);
            const float rx = fminf(a.z, gbx.z), ry = fminf(a.w, gbx.w);
            const float iw = fmaxf(rx - lx, 0.f), ih = fmaxf(ry - ly, 0.f);
            const float inter = iw * ih;
            const float uni = area_a + sArea[matched] - inter;
            it = inter / fmaxf(uni, 1e-9f);
        }
        posi = pos ? 1 : 0;
        const float4 rt = pos ? sGT[matched] : make_float4(0.f, 0.f, 0.f, 0.f);

        // ---- QFL: uniform negative pass + single target-class correction ----
        {
            const float4* cp = (const float4*)(cls_preds + ((size_t)b * NANCH + n) * NCLS);
            float xsel = 0.f;
#pragma unroll
            for (int v = 0; v < 5; v++) {
                const float4 xv = __ldg(&cp[v]);
                const float xs[4] = { xv.x, xv.y, xv.z, xv.w };
#pragma unroll
                for (int j = 0; j < 4; j++) {
                    const int c = v * 4 + j;
                    const float x = xs[j];
                    const float e = __expf(x);
                    const float d = 1.0f + e;
                    const float sp = __logf(d);
                    const float r = __fdividef(1.0f, d);
                    const float w = fmaf(it, 1.0f - 2.0f * r, r);
                    qfl += (w * w) * sp;
                    if (c == cls_t) xsel = x;
                }
            }
            {
                const float e = __expf(xsel);
                const float d = 1.0f + e;
                const float sp = __logf(d);
                const float r = __fdividef(1.0f, d);
                const float wn = fmaf(it, 1.0f - 2.0f * r, r);
                const float neg = (wn * wn) * sp;
                const float psig = 1.0f - r;
                const float wp = fmaf(it, 1.0f - 2.0f * psig, psig);
                const float posv = (wp * wp) * (sp - xsel);
                qfl += posv - neg;
            }
        }

        // ---- DFL + decode + GIoU: positives only (validated accurate math) ----
        if (pos) {
            const float4* rp = (const float4*)(reg_preds + ((size_t)b * NANCH + n) * 4 * NBINS);
            const float rts[4] = { rt.x, rt.y, rt.z, rt.w };
            float delta[4];
#pragma unroll
            for (int s = 0; s < 4; s++) {
                float l[16];
#pragma unroll
                for (int v = 0; v < 4; v++) {
                    const float4 lv = __ldg(&rp[s * 4 + v]);
                    l[v * 4 + 0] = lv.x; l[v * 4 + 1] = lv.y;
                    l[v * 4 + 2] = lv.z; l[v * 4 + 3] = lv.w;
                }
                float mx = l[0];
#pragma unroll
                for (int k = 1; k < 16; k++) mx = fmaxf(mx, l[k]);

                const float ts = rts[s] * 15.f;
                int li = (int)ts; li = max(0, min(li, 14));
                const int ri = li + 1;
                const float wr = ts - (float)li, wl = 1.f - wr;

                float se = 0.f, ne = 0.f, lli = 0.f, lri = 0.f;
#pragma unroll
                for (int k = 0; k < 16; k++) {
                    const float ek = expf(l[k] - mx);
                    se += ek; ne += ek * (float)k;
                    if (k == li) lli = l[k];
                    if (k == ri) lri = l[k];
                }
                const float lz = mx + logf(se);
                dfl += -(wl * (lli - lz) + wr * (lri - lz));
                delta[s] = ne / (se * 15.f);
            }
            const float pcx = delta[0] * aw + acx;
            const float pcy = delta[1] * ah + acy;
            const float pw = expf(delta[2]) * aw;
            const float ph = expf(delta[3]) * ah;
            const float px1 = pcx - 0.5f * pw, py1 = pcy - 0.5f * ph;
            const float px2 = pcx + 0.5f * pw, py2 = pcy + 0.5f * ph;
            const float lx = fmaxf(px1, rt.x), ly = fmaxf(py1, rt.y);
            const float rx = fminf(px2, rt.z), ry = fminf(py2, rt.w);
            const float iw = fmaxf(rx - lx, 0.f), ih = fmaxf(ry - ly, 0.f);
            const float inter = iw * ih;
            const float pa = (px2 - px1) * (py2 - py1);
            const float ga = (rt.z - rt.x) * (rt.w - rt.y);
            const float uni = pa + ga - inter;
            const float iou = inter / fmaxf(uni, 1e-9f);
            const float ex1 = fminf(px1, rt.x), ey1 = fminf(py1, rt.y);
            const float ex2 = fmaxf(px2, rt.z), ey2 = fmaxf(py2, rt.w);
            const float ew = fmaxf(ex2 - ex1, 0.f), eh = fmaxf(ey2 - ey1, 0.f);
            const float enc = ew * eh;
            const float gv = iou - (enc - uni) / fmaxf(enc, 1e-9f);
            giou_l = 1.f - gv;
        }
    }

    // ---- reduction: warp -> block -> global double atomics ----
#pragma unroll
    for (int off = 16; off > 0; off >>= 1) {
        qfl    += __shfl_xor_sync(0xffffffffu, qfl,    off);
        dfl    += __shfl_xor_sync(0xffffffffu, dfl,    off);
        giou_l += __shfl_xor_sync(0xffffffffu, giou_l, off);
        posi   += __shfl_xor_sync(0xffffffffu, posi,   off);
    }
    __shared__ float rq[8], rd[8], rg[8];
    __shared__ int   rp_[8];
    const int warp = threadIdx.x >> 5;
    const int lane = threadIdx.x & 31;
    if (lane == 0) { rq[warp] = qfl; rd[warp] = dfl; rg[warp] = giou_l; rp_[warp] = posi; }
    __syncthreads();
    if (threadIdx.x == 0) {
        float q = 0.f, dd = 0.f, gg = 0.f; int pp = 0;
#pragma unroll
        for (int wi = 0; wi < LOSS_BLK / 32; wi++) {
            q += rq[wi]; dd += rd[wi]; gg += rg[wi]; pp += rp_[wi];
        }
        if (q  != 0.f) atomicAdd(&g_qfl,  (double)q);
        if (dd != 0.f) atomicAdd(&g_dfl,  (double)dd);
        if (gg != 0.f) atomicAdd(&g_giou, (double)gg);
        if (pp != 0)   atomicAdd(&g_pos,  pp);
        __threadfence();
        const unsigned int ticket = atomicAdd(&g_count, 1u);
        if (ticket == NBLOCKS - 1) {
            const int pos = *((volatile int*)&g_pos);
            const double sq = *((volatile double*)&g_qfl);
            const double sd = *((volatile double*)&g_dfl);
            const double sg = *((volatile double*)&g_giou);
            const double npc = (double)max(pos, 1);
            const double qv = sq / npc;
            double df = sd / (double)max(4 * pos, 1);
            df = fmin(fmax(df, 0.0), 1.0);
            const double gi = sg / npc;
            out[0] = (float)(qv + df + gi);
            out[1] = (float)qv;
            out[2] = (float)df;
            out[3] = (float)gi;
            g_qfl = 0.0; g_dfl = 0.0; g_giou = 0.0; g_pos = 0;
            __threadfence();
            g_count = 0u;
        }
    }
}

extern "C" void kernel_launch(void* const* d_in, const int* in_sizes, int n_in,
                              void* d_out, int out_size) {
    const float*  cls_preds = (const float*)d_in[0];
    const float*  reg_preds = (const float*)d_in[1];
    const float4* gt_boxes  = (const float4*)d_in[3];
    const int*    gt_labels = (const int*)d_in[4];
    float* out = (float*)d_out;

    match_kernel<<<NGT, 128>>>(gt_boxes);
    dim3 grid(LOSS_GX, BATCH);
    loss_kernel<<<grid, LOSS_BLK>>>(cls_preds, reg_preds, gt_boxes, gt_labels, out);
}